// round 14
// baseline (speedup 1.0000x reference)
#include <cuda_runtime.h>
#include <cuda_bf16.h>

// ---------------- problem constants ----------------
#define AA        9
#define HH        128
#define WW        192
#define HW        (HH * WW)          // 24576
#define NTOT      (HW * AA)          // 221184
#define PRE_N     6000
#define POST_N    300
#define MASK_W    94                 // ceil(6000/64)
#define CAP       8192               // candidate slot capacity
#define HIST_BITS 16
#define HIST_SZ   (1u << HIST_BITS)
#define NMS_TH    0.7f
#define AMB_CAP   1024

// ---------------- static device scratch (no runtime alloc) ----------------
__device__ float4             g_boxes[NTOT];        // decoded clipped boxes, [a*HW+pix]
__device__ unsigned           g_sbits[NTOT];        // score bits (0 if invalid)
__device__ unsigned           g_hist[HIST_SZ];      // zeroed by k_thresh after use
__device__ unsigned           g_rankbase[HIST_SZ];  // fully overwritten by k_thresh
__device__ unsigned           g_binfill[HIST_SZ];   // zeroed by k_thresh before compact
__device__ unsigned long long g_slot[CAP];          // rank-region scatter; guarded by total
__device__ unsigned           g_T;                  // threshold histogram bin
__device__ float4             g_top_boxes[PRE_N];   // rows < total overwritten by k_rank
__device__ unsigned long long g_invalid[MASK_W];    // zeroed by k_decode
__device__ unsigned long long g_mask[(size_t)PRE_N * MASK_W];  // garbage-tolerant below diag
__device__ unsigned           g_amb_count;          // zeroed by k_decode
__device__ unsigned           g_amb[AMB_CAP];

// 9 base anchors (ratios 0.5,1,2 x scales 8,16,32), numpy semantics:
// r=0.5 -> (ws,hs)=(23,12); r=1 -> (16,16); r=2 -> (11,22).
__constant__ float4 c_anchors[AA] = {
    { -84.f,  -40.f,  99.f,  55.f},
    {-176.f,  -88.f, 191.f, 103.f},
    {-360.f, -184.f, 375.f, 199.f},
    { -56.f,  -56.f,  71.f,  71.f},
    {-120.f, -120.f, 135.f, 135.f},
    {-248.f, -248.f, 263.f, 263.f},
    { -36.f,  -80.f,  51.f,  95.f},
    { -80.f, -168.f,  95.f, 183.f},
    {-168.f, -344.f, 183.f, 359.f}
};

// ---------------- K1: decode (4 pix/thread, float4) + histogram + scratch clear ----
__global__ void k_decode(const float* __restrict__ scores,
                         const float* __restrict__ deltas,
                         const float* __restrict__ im_info) {
    int v = blockIdx.x * blockDim.x + threadIdx.x;   // 0 .. NTOT/4-1

    if (v < MASK_W) g_invalid[v] = 0ull;
    if (v == 0)     g_amb_count = 0u;

    if (v >= NTOT / 4) return;
    int t0   = v * 4;
    int a    = t0 / HW;
    int pix0 = t0 % HW;
    int y = pix0 / WW, x0 = pix0 % WW;

    float4 scv = *(const float4*)&scores[(AA + a) * HW + pix0];
    float4 dxv = *(const float4*)&deltas[(4 * a + 0) * HW + pix0];
    float4 dyv = *(const float4*)&deltas[(4 * a + 1) * HW + pix0];
    float4 dwv = *(const float4*)&deltas[(4 * a + 2) * HW + pix0];
    float4 dhv = *(const float4*)&deltas[(4 * a + 3) * HW + pix0];

    float imh = __ldg(&im_info[0]), imw = __ldg(&im_info[1]), iscale = __ldg(&im_info[2]);
    float min_sz = 16.f * iscale;

    float4 an = c_anchors[a];
    float wdt = an.z - an.x + 1.f, hgt = an.w - an.y + 1.f;
    float cy  = an.y + 16.f * y + 0.5f * hgt;
    float cx0 = an.x + 0.5f * wdt;

    float scs[4] = {scv.x, scv.y, scv.z, scv.w};
    float dxs[4] = {dxv.x, dxv.y, dxv.z, dxv.w};
    float dys[4] = {dyv.x, dyv.y, dyv.z, dyv.w};
    float dws[4] = {dwv.x, dwv.y, dwv.z, dwv.w};
    float dhs[4] = {dhv.x, dhv.y, dhv.z, dhv.w};
    unsigned sbo[4];

    #pragma unroll
    for (int e = 0; e < 4; e++) {
        float dw = fminf(fmaxf(dws[e], -10.f), 10.f);
        float dh = fminf(fmaxf(dhs[e], -10.f), 10.f);
        float cx = cx0 + 16.f * (x0 + e);

        float pcx = dxs[e] * wdt + cx;
        float pcy = dys[e] * hgt + cy;
        float pw  = expf(dw) * wdt;
        float ph  = expf(dh) * hgt;

        float x1 = fminf(fmaxf(pcx - 0.5f * pw, 0.f), imw - 1.f);
        float y1 = fminf(fmaxf(pcy - 0.5f * ph, 0.f), imh - 1.f);
        float x2 = fminf(fmaxf(pcx + 0.5f * pw, 0.f), imw - 1.f);
        float y2 = fminf(fmaxf(pcy + 0.5f * ph, 0.f), imh - 1.f);

        bool valid = (x2 - x1 + 1.f >= min_sz) && (y2 - y1 + 1.f >= min_sz);

        g_boxes[t0 + e] = make_float4(x1, y1, x2, y2);
        unsigned sb = (valid && scs[e] > 0.f) ? __float_as_uint(scs[e]) : 0u;
        sbo[e] = sb;
        atomicAdd(&g_hist[sb >> (32 - HIST_BITS)], 1u);
    }
    ((uint4*)g_sbits)[v] = make_uint4(sbo[0], sbo[1], sbo[2], sbo[3]);
}

// ---------------- K2: threshold bin + suffix-sum rank bases + clears ----------------
// g_rankbase[b] = number of histogram entries in bins strictly above b.
__global__ void k_thresh() {
    __shared__ unsigned csum[1024];
    __shared__ unsigned ssum[1024];
    const int CHUNK = HIST_SZ / 1024;   // 64
    int tid = threadIdx.x;
    unsigned s = 0;
    int base = tid * CHUNK;
    unsigned hloc[CHUNK / 4 * 4];       // cache the chunk (64 entries)
    #pragma unroll 4
    for (int i = 0; i < CHUNK; i++) { hloc[i] = g_hist[base + i]; s += hloc[i]; }
    csum[tid] = s;
    ssum[tid] = s;
    __syncthreads();

    // inclusive suffix scan of csum into ssum (Hillis-Steele)
    for (int off = 1; off < 1024; off <<= 1) {
        unsigned add = (tid + off < 1024) ? ssum[tid + off] : 0u;
        __syncthreads();
        ssum[tid] += add;
        __syncthreads();
    }

    // per-bin rank bases within my chunk (top-down)
    unsigned run = ssum[tid] - csum[tid];   // total in chunks above mine
    for (int i = CHUNK - 1; i >= 0; i--) {
        g_rankbase[base + i] = run;
        run += hloc[i];
    }

    if (tid == 0) {
        unsigned acc = 0;
        int c;
        for (c = 1023; c >= 0; c--) {
            if (acc + csum[c] >= PRE_N) break;
            acc += csum[c];
        }
        unsigned T = 0;
        if (c >= 0) {
            int b;
            for (b = c * CHUNK + CHUNK - 1; b >= c * CHUNK; b--) {
                acc += g_hist[b];
                if (acc >= PRE_N) break;
            }
            if (b < c * CHUNK) b = c * CHUNK;
            T = (unsigned)b;
        }
        g_T = T;
    }
    __syncthreads();                    // all reads of g_hist complete

    uint4 z = make_uint4(0u, 0u, 0u, 0u);
    uint4* hv = (uint4*)&g_hist[base];
    uint4* fv = (uint4*)&g_binfill[base];
    #pragma unroll
    for (int i = 0; i < CHUNK / 4; i++) { hv[i] = z; fv[i] = z; }
}

// ---------------- K3: compact into per-bin rank regions ----------------
__global__ void k_compact() {
    int v = blockIdx.x * blockDim.x + threadIdx.x;
    if (v >= NTOT / 4) return;
    uint4 sbv = ((const uint4*)g_sbits)[v];
    unsigned T = g_T;
    unsigned sbs[4] = {sbv.x, sbv.y, sbv.z, sbv.w};
    #pragma unroll
    for (int e = 0; e < 4; e++) {
        unsigned sb = sbs[e];
        unsigned bin = sb >> (32 - HIST_BITS);
        if (sb != 0u && bin >= T) {
            unsigned off  = atomicAdd(&g_binfill[bin], 1u);
            unsigned slot = g_rankbase[bin] + off;
            if (slot < CAP) {
                int t = 4 * v + e;
                int a = t / HW, pix = t % HW;
                unsigned n = (unsigned)(pix * AA + a);   // reference flat index
                g_slot[slot] = ((unsigned long long)sb << 32) | (0xFFFFFFFFu - n);
            }
        }
    }
}

// ---------------- K4: exact rank within bin region + gather ----------------
// rank(key) = rankbase[bin] + #{keys in bin region > key}. Keys are unique
// (index in low bits) so ranks are a complete permutation -> exact top_k order
// with jax's stable tie-break (higher score first, then lower index).
__global__ void k_rank() {
    int q = blockIdx.x * blockDim.x + threadIdx.x;
    unsigned T = g_T;
    unsigned total = g_rankbase[T] + g_binfill[T];
    if (total > CAP) total = CAP;

    if (q == 0) {
        // mark any unfilled ranks invalid (only when < 6000 candidates exist)
        for (unsigned r = total; r < PRE_N; r++)
            atomicOr(&g_invalid[r >> 6], 1ull << (r & 63));
    }
    if (q >= (int)total) return;

    unsigned long long key = g_slot[q];
    unsigned bin  = (unsigned)(key >> 48);
    unsigned base = g_rankbase[bin];
    unsigned cnt  = g_binfill[bin];
    unsigned end  = base + cnt;
    if (end > CAP) end = CAP;

    unsigned rank = base;
    unsigned k2 = base;
    #pragma unroll 4
    for (; k2 < end; k2++)
        rank += (__ldg(&g_slot[k2]) > key) ? 1u : 0u;

    if (rank < PRE_N) {
        unsigned n = 0xFFFFFFFFu - (unsigned)key;
        int a = n % AA, pix = n / AA;
        g_top_boxes[rank] = g_boxes[a * HW + pix];
    }
}

// ---------------- K5: IoU suppression bitmask, upper triangle only, division-free ----
// Greedy-scan invariant: when candidate i is selected every bit < i is already
// set in the state, and garbage words w < i>>6 cover only columns < i, so OR-ing
// uninitialized/stale lower-triangle words is harmless -> cb<rb blocks write NOTHING.
// Decision: RN(inter/den) > 0.7f  <=>  inter >= (0.7f + 2^-25)*den (exact reals).
// cheap = fma(-0.7f, den, inter), err <= 2^-24|cheap|; s = 2^-25*den exact.
// Band pairs -> fixup list, resolved with the reference's own fp32 division.
__global__ void k_mask() {
    __shared__ float4 col[64];
    __shared__ float  carea_s[64];
    int cb = blockIdx.x, rb = blockIdx.y;
    if (cb < rb) return;
    int t = threadIdx.x;
    int row = rb * 64 + t;
    int c0 = cb * 64;
    int ci = c0 + t;
    float4 cv = (ci < PRE_N) ? __ldg(&g_top_boxes[ci]) : make_float4(0.f, 0.f, 0.f, 0.f);
    col[t] = cv;
    carea_s[t] = (cv.z - cv.x) * (cv.w - cv.y);
    __syncthreads();
    if (row >= PRE_N) return;
    float4 rbx = __ldg(&g_top_boxes[row]);
    float rarea = (rbx.z - rbx.x) * (rbx.w - rbx.y);
    unsigned long long bits = 0ull;
    int ncols = min(64, PRE_N - c0);
    #pragma unroll 4
    for (int c = 0; c < ncols; c++) {
        float4 cbx = col[c];
        float xx1 = fmaxf(rbx.x, cbx.x), yy1 = fmaxf(rbx.y, cbx.y);
        float xx2 = fminf(rbx.z, cbx.z), yy2 = fminf(rbx.w, cbx.w);
        float w = fmaxf(xx2 - xx1, 0.f), h = fmaxf(yy2 - yy1, 0.f);
        float inter = w * h;
        float den   = (rarea + carea_s[c]) - inter;
        float cheap = fmaf(-NMS_TH, den, inter);
        float s     = 0x1p-25f * den;
        bool cond   = (den > 0.f) && (cheap > s);
        float margin = fmaf(0x1p-23f, fabsf(cheap), 0x1p-30f * den);
        if (den > 0.f && fabsf(cheap - s) <= margin) {
            unsigned p = atomicAdd(&g_amb_count, 1u);
            if (p < AMB_CAP) g_amb[p] = (unsigned)row * 8192u + (unsigned)(c0 + c);
        }
        if (cond) bits |= (1ull << c);
    }
    g_mask[(size_t)row * MASK_W + cb] = bits;
}

// ---------------- K6: fixup + serial greedy NMS (1 warp, register mask) + output ----
__device__ __forceinline__ void prefetch_rows(int i, int l) {
    if (l < 30) {
        #pragma unroll
        for (int k = 0; k < 2; k++) {
            int p = l + 30 * k;                 // 0..59
            int d = 1 + p / 6;                  // 1..10
            int line = p % 6;                   // 0..5
            int r2 = i + d;
            if (r2 < PRE_N) {
                const char* ptr = (const char*)(g_mask + (size_t)r2 * MASK_W) + line * 128;
                asm volatile("prefetch.global.L1 [%0];" :: "l"(ptr));
            }
        }
    }
}

__global__ void __launch_bounds__(32, 1) k_nms_out(float* __restrict__ out) {
    __shared__ int kept[POST_N];
    int l = threadIdx.x;

    unsigned namb = g_amb_count;
    if (namb > AMB_CAP) namb = AMB_CAP;
    for (unsigned e = l; e < namb; e += 32) {
        unsigned pk = g_amb[e];
        int row = (int)(pk / 8192u), colk = (int)(pk % 8192u);
        float4 rbx = g_top_boxes[row];
        float4 cbx = g_top_boxes[colk];
        float rarea = (rbx.z - rbx.x) * (rbx.w - rbx.y);
        float carea = (cbx.z - cbx.x) * (cbx.w - cbx.y);
        float xx1 = fmaxf(rbx.x, cbx.x), yy1 = fmaxf(rbx.y, cbx.y);
        float xx2 = fminf(rbx.z, cbx.z), yy2 = fminf(rbx.w, cbx.w);
        float w = fmaxf(xx2 - xx1, 0.f), h = fmaxf(yy2 - yy1, 0.f);
        float inter = w * h;
        float den   = (rarea + carea) - inter;
        float iou   = __fdiv_rn(inter, den);
        unsigned long long bit = 1ull << (colk & 63);
        unsigned long long* word = &g_mask[(size_t)row * MASK_W + (colk >> 6)];
        if (iou > NMS_TH) atomicOr(word, bit);
        else              atomicAnd(word, ~bit);
    }
    __threadfence_block();
    __syncwarp();

    prefetch_rows(-1, l);

    unsigned long long s0 = g_invalid[l];
    unsigned long long s1 = g_invalid[l + 32];
    unsigned long long s2 = (l < 30) ? g_invalid[l + 64] : ~0ull;
    if (l == 29) s2 |= ~((1ull << 48) - 1ull);

    int cnt = 0;
    while (cnt < POST_N) {
        unsigned long long c0 = ~s0, c1 = ~s1, c2 = ~s2;
        unsigned cand;
        if (c0)      cand = (unsigned)((l << 6)        + __ffsll((long long)c0) - 1);
        else if (c1) cand = (unsigned)(((l + 32) << 6) + __ffsll((long long)c1) - 1);
        else if (c2) cand = (unsigned)(((l + 64) << 6) + __ffsll((long long)c2) - 1);
        else         cand = 0x7FFFFFFFu;
        unsigned i = __reduce_min_sync(0xFFFFFFFFu, cand);
        if (i >= PRE_N) break;

        if (l == 0) kept[cnt] = (int)i;
        cnt++;

        prefetch_rows((int)i, l);

        const unsigned long long* row = g_mask + (size_t)i * MASK_W;
        s0 |= __ldg(&row[l]);
        s1 |= __ldg(&row[l + 32]);
        if (l < 30) s2 |= __ldg(&row[l + 64]);
    }
    __syncwarp();

    for (int r = l; r < POST_N; r += 32) {
        float4 b4 = (r < cnt) ? g_top_boxes[kept[r]] : make_float4(0.f, 0.f, 0.f, 0.f);
        out[r * 5 + 0] = 0.f;
        out[r * 5 + 1] = b4.x;
        out[r * 5 + 2] = b4.y;
        out[r * 5 + 3] = b4.z;
        out[r * 5 + 4] = b4.w;
    }
}

// ---------------- launch ----------------
extern "C" void kernel_launch(void* const* d_in, const int* in_sizes, int n_in,
                              void* d_out, int out_size) {
    const float* scores  = (const float*)d_in[0];
    const float* deltas  = (const float*)d_in[1];
    const float* im_info = (const float*)d_in[2];
    float* out = (float*)d_out;
    (void)in_sizes; (void)n_in; (void)out_size;

    k_decode <<<(NTOT / 4 + 255) / 256, 256>>>(scores, deltas, im_info);
    k_thresh <<<1, 1024>>>();
    k_compact<<<(NTOT / 4 + 255) / 256, 256>>>();
    k_rank   <<<CAP / 128, 128>>>();
    k_mask   <<<dim3(MASK_W, MASK_W), 64>>>();
    k_nms_out<<<1, 32>>>(out);
}

// round 17
// speedup vs baseline: 1.1107x; 1.1107x over previous
#include <cuda_runtime.h>
#include <cuda_bf16.h>

// ---------------- problem constants ----------------
#define AA        9
#define HH        128
#define WW        192
#define HW        (HH * WW)          // 24576
#define NTOT      (HW * AA)          // 221184
#define PRE_N     6000
#define POST_N    300
#define MASK_W    94                 // ceil(6000/64)
#define CAP       8192               // candidate slot capacity
#define HIST_BITS 16
#define HIST_SZ   (1u << HIST_BITS)
#define NMS_TH    0.7f
#define AMB_CAP   1024
#define CR_BLOCKS ((NTOT / 4 + 255) / 256)   // 216 blocks, single wave

// ---------------- static device scratch (no runtime alloc) ----------------
__device__ float4             g_boxes[NTOT];        // decoded clipped boxes, [a*HW+pix]
__device__ unsigned           g_sbits[NTOT];        // score bits (0 if invalid)
__device__ unsigned           g_hist[HIST_SZ];      // zeroed by k_thresh after use
__device__ unsigned           g_rankbase[HIST_SZ];  // fully overwritten by k_thresh
__device__ unsigned           g_binfill[HIST_SZ];   // zeroed by k_thresh before compact
__device__ unsigned long long g_slot[CAP];          // rank-region scatter; guarded by total
__device__ unsigned           g_T;                  // threshold histogram bin
__device__ float4             g_top_boxes[PRE_N];   // rows < total overwritten by rank phase
__device__ unsigned long long g_invalid[MASK_W];    // zeroed by k_decode
__device__ unsigned long long g_mask[(size_t)PRE_N * MASK_W];  // garbage-tolerant below diag
__device__ unsigned           g_amb_count;          // zeroed by k_decode
__device__ unsigned           g_amb[AMB_CAP];
__device__ unsigned           g_bar2;               // grid barrier, zeroed by k_decode

// 9 base anchors (ratios 0.5,1,2 x scales 8,16,32), numpy semantics:
// r=0.5 -> (ws,hs)=(23,12); r=1 -> (16,16); r=2 -> (11,22).
__constant__ float4 c_anchors[AA] = {
    { -84.f,  -40.f,  99.f,  55.f},
    {-176.f,  -88.f, 191.f, 103.f},
    {-360.f, -184.f, 375.f, 199.f},
    { -56.f,  -56.f,  71.f,  71.f},
    {-120.f, -120.f, 135.f, 135.f},
    {-248.f, -248.f, 263.f, 263.f},
    { -36.f,  -80.f,  51.f,  95.f},
    { -80.f, -168.f,  95.f, 183.f},
    {-168.f, -344.f, 183.f, 359.f}
};

// ---------------- K1: decode (4 pix/thread, float4) + histogram + scratch clear ----
__global__ void __launch_bounds__(256) k_decode(const float* __restrict__ scores,
                                                const float* __restrict__ deltas,
                                                const float* __restrict__ im_info) {
    int v = blockIdx.x * blockDim.x + threadIdx.x;   // 0 .. NTOT/4-1

    if (v < MASK_W) g_invalid[v] = 0ull;
    if (v == 0)     { g_amb_count = 0u; g_bar2 = 0u; }

    if (v >= NTOT / 4) return;
    int t0   = v * 4;
    int a    = t0 / HW;
    int pix0 = t0 % HW;
    int y = pix0 / WW, x0 = pix0 % WW;

    float4 scv = *(const float4*)&scores[(AA + a) * HW + pix0];
    float4 dxv = *(const float4*)&deltas[(4 * a + 0) * HW + pix0];
    float4 dyv = *(const float4*)&deltas[(4 * a + 1) * HW + pix0];
    float4 dwv = *(const float4*)&deltas[(4 * a + 2) * HW + pix0];
    float4 dhv = *(const float4*)&deltas[(4 * a + 3) * HW + pix0];

    float imh = __ldg(&im_info[0]), imw = __ldg(&im_info[1]), iscale = __ldg(&im_info[2]);
    float min_sz = 16.f * iscale;

    float4 an = c_anchors[a];
    float wdt = an.z - an.x + 1.f, hgt = an.w - an.y + 1.f;
    float cy  = an.y + 16.f * y + 0.5f * hgt;
    float cx0 = an.x + 0.5f * wdt;

    float scs[4] = {scv.x, scv.y, scv.z, scv.w};
    float dxs[4] = {dxv.x, dxv.y, dxv.z, dxv.w};
    float dys[4] = {dyv.x, dyv.y, dyv.z, dyv.w};
    float dws[4] = {dwv.x, dwv.y, dwv.z, dwv.w};
    float dhs[4] = {dhv.x, dhv.y, dhv.z, dhv.w};
    unsigned sbo[4];

    #pragma unroll
    for (int e = 0; e < 4; e++) {
        float dw = fminf(fmaxf(dws[e], -10.f), 10.f);
        float dh = fminf(fmaxf(dhs[e], -10.f), 10.f);
        float cx = cx0 + 16.f * (x0 + e);

        float pcx = dxs[e] * wdt + cx;
        float pcy = dys[e] * hgt + cy;
        float pw  = expf(dw) * wdt;
        float ph  = expf(dh) * hgt;

        float x1 = fminf(fmaxf(pcx - 0.5f * pw, 0.f), imw - 1.f);
        float y1 = fminf(fmaxf(pcy - 0.5f * ph, 0.f), imh - 1.f);
        float x2 = fminf(fmaxf(pcx + 0.5f * pw, 0.f), imw - 1.f);
        float y2 = fminf(fmaxf(pcy + 0.5f * ph, 0.f), imh - 1.f);

        bool valid = (x2 - x1 + 1.f >= min_sz) && (y2 - y1 + 1.f >= min_sz);

        g_boxes[t0 + e] = make_float4(x1, y1, x2, y2);
        unsigned sb = (valid && scs[e] > 0.f) ? __float_as_uint(scs[e]) : 0u;
        sbo[e] = sb;
        atomicAdd(&g_hist[sb >> (32 - HIST_BITS)], 1u);
    }
    ((uint4*)g_sbits)[v] = make_uint4(sbo[0], sbo[1], sbo[2], sbo[3]);
}

// ---------------- K2: suffix-sum rank bases + PARALLEL threshold find + clears ------
// g_rankbase[b] = number of histogram entries in bins strictly above b.
// T is the unique bin with rankbase[T] < PRE_N <= rankbase[T]+hist[T].
// __launch_bounds__(1024,1): ptxas MUST fit 64 regs/thread (spill hloc if needed)
// -> fixes "too many resources requested for launch".
__global__ void __launch_bounds__(1024, 1) k_thresh() {
    __shared__ unsigned csum[1024];
    __shared__ unsigned ssum[1024];
    const int CHUNK = HIST_SZ / 1024;   // 64
    int tid = threadIdx.x;
    unsigned s = 0;
    int base = tid * CHUNK;
    unsigned hloc[CHUNK];               // cache the chunk (may spill; bounded regs)
    #pragma unroll 4
    for (int i = 0; i < CHUNK; i++) { hloc[i] = g_hist[base + i]; s += hloc[i]; }
    csum[tid] = s;
    ssum[tid] = s;
    if (tid == 0) g_T = 0u;             // default when total < PRE_N
    __syncthreads();

    // inclusive suffix scan of csum into ssum (Hillis-Steele)
    for (int off = 1; off < 1024; off <<= 1) {
        unsigned add = (tid + off < 1024) ? ssum[tid + off] : 0u;
        __syncthreads();
        ssum[tid] += add;
        __syncthreads();
    }

    // per-bin rank bases within my chunk (top-down) + parallel threshold detect
    unsigned run = ssum[tid] - csum[tid];   // total in chunks above mine
    for (int i = CHUNK - 1; i >= 0; i--) {
        g_rankbase[base + i] = run;
        if (run < PRE_N && run + hloc[i] >= PRE_N)
            g_T = (unsigned)(base + i);     // unique writer
        run += hloc[i];
    }
    __syncthreads();                    // all reads of g_hist complete

    uint4 z = make_uint4(0u, 0u, 0u, 0u);
    uint4* hv = (uint4*)&g_hist[base];
    uint4* fv = (uint4*)&g_binfill[base];
    #pragma unroll
    for (int i = 0; i < CHUNK / 4; i++) { hv[i] = z; fv[i] = z; }
}

// ---------------- K3: FUSED compact -> grid barrier -> warp-per-candidate rank -----
// Phase 1: scatter candidates into per-bin rank regions (g_slot).
// Barrier: 216 blocks x 256 thr co-resident (single wave) -> spin barrier safe;
//          release fence + atomic arrive, spin on RMW, acquire fence.
// Phase 2: rank(key) = rankbase[bin] + #{keys in bin region > key}; keys unique
//          -> exact jax top_k order incl. stable tie-break. Warp per candidate,
//          lanes stride the bin region coalesced, in-warp reduce.
__global__ void __launch_bounds__(256, 1) k_compact_rank() {
    int v = blockIdx.x * blockDim.x + threadIdx.x;

    // ---- phase 1: compact ----
    if (v < NTOT / 4) {
        uint4 sbv = ((const uint4*)g_sbits)[v];
        unsigned T = g_T;
        unsigned sbs[4] = {sbv.x, sbv.y, sbv.z, sbv.w};
        #pragma unroll
        for (int e = 0; e < 4; e++) {
            unsigned sb = sbs[e];
            unsigned bin = sb >> (32 - HIST_BITS);
            if (sb != 0u && bin >= T) {
                unsigned off  = atomicAdd(&g_binfill[bin], 1u);
                unsigned slot = g_rankbase[bin] + off;
                if (slot < CAP) {
                    int t = 4 * v + e;
                    int a = t / HW, pix = t % HW;
                    unsigned n = (unsigned)(pix * AA + a);   // reference flat index
                    g_slot[slot] = ((unsigned long long)sb << 32) | (0xFFFFFFFFu - n);
                }
            }
        }
    }

    // ---- grid-wide barrier (release/acquire) ----
    __syncthreads();
    __threadfence();
    if (threadIdx.x == 0) {
        atomicAdd(&g_bar2, 1u);
        while (atomicAdd(&g_bar2, 0u) < (unsigned)gridDim.x) { __nanosleep(64); }
    }
    __syncthreads();
    __threadfence();

    // ---- phase 2: rank + gather ----
    unsigned T = g_T;
    unsigned total = g_rankbase[T] + g_binfill[T];
    if (total > CAP) total = CAP;

    int gwarp = (blockIdx.x * blockDim.x + threadIdx.x) >> 5;
    int lane  = threadIdx.x & 31;
    int nwarps = (gridDim.x * blockDim.x) >> 5;   // 1728

    if (gwarp == 0) {
        // mark any unfilled ranks invalid (only when < 6000 candidates exist)
        for (unsigned r = total + lane; r < PRE_N; r += 32)
            atomicOr(&g_invalid[r >> 6], 1ull << (r & 63));
    }

    for (unsigned w = (unsigned)gwarp; w < total; w += (unsigned)nwarps) {
        unsigned long long key = g_slot[w];
        unsigned bin  = (unsigned)(key >> 48);
        unsigned base = g_rankbase[bin];
        unsigned cnt  = g_binfill[bin];
        unsigned end  = base + cnt;
        if (end > CAP) end = CAP;

        unsigned local = 0;
        for (unsigned k = base + lane; k < end; k += 32)
            local += (__ldg(&g_slot[k]) > key) ? 1u : 0u;
        unsigned greater = __reduce_add_sync(0xFFFFFFFFu, local);

        if (lane == 0) {
            unsigned rank = base + greater;
            if (rank < PRE_N) {
                unsigned n = 0xFFFFFFFFu - (unsigned)key;
                int a = n % AA, pix = n / AA;
                g_top_boxes[rank] = g_boxes[a * HW + pix];
            }
        }
    }
}

// ---------------- K4 (PROFILED SLOT): IoU bitmask, upper triangle, division-free ----
// Greedy-scan invariant: when candidate i is selected every bit < i is already
// set in the state, and garbage words w < i>>6 cover only columns < i, so OR-ing
// uninitialized/stale lower-triangle words is harmless -> cb<rb blocks write NOTHING.
// Decision: RN(inter/den) > 0.7f  <=>  inter >= (0.7f + 2^-25)*den (exact reals).
// cheap = fma(-0.7f, den, inter), err <= 2^-24|cheap|; s = 2^-25*den exact.
// Band pairs -> fixup list, resolved with the reference's own fp32 division.
__global__ void __launch_bounds__(64) k_mask() {
    __shared__ float4 col[64];
    __shared__ float  carea_s[64];
    int cb = blockIdx.x, rb = blockIdx.y;
    if (cb < rb) return;
    int t = threadIdx.x;
    int row = rb * 64 + t;
    int c0 = cb * 64;
    int ci = c0 + t;
    float4 cv = (ci < PRE_N) ? __ldg(&g_top_boxes[ci]) : make_float4(0.f, 0.f, 0.f, 0.f);
    col[t] = cv;
    carea_s[t] = (cv.z - cv.x) * (cv.w - cv.y);
    __syncthreads();
    if (row >= PRE_N) return;
    float4 rbx = __ldg(&g_top_boxes[row]);
    float rarea = (rbx.z - rbx.x) * (rbx.w - rbx.y);
    unsigned long long bits = 0ull;
    int ncols = min(64, PRE_N - c0);
    #pragma unroll 4
    for (int c = 0; c < ncols; c++) {
        float4 cbx = col[c];
        float xx1 = fmaxf(rbx.x, cbx.x), yy1 = fmaxf(rbx.y, cbx.y);
        float xx2 = fminf(rbx.z, cbx.z), yy2 = fminf(rbx.w, cbx.w);
        float w = fmaxf(xx2 - xx1, 0.f), h = fmaxf(yy2 - yy1, 0.f);
        float inter = w * h;
        float den   = (rarea + carea_s[c]) - inter;
        float cheap = fmaf(-NMS_TH, den, inter);
        float s     = 0x1p-25f * den;
        bool cond   = (den > 0.f) && (cheap > s);
        float margin = fmaf(0x1p-23f, fabsf(cheap), 0x1p-30f * den);
        if (den > 0.f && fabsf(cheap - s) <= margin) {
            unsigned p = atomicAdd(&g_amb_count, 1u);
            if (p < AMB_CAP) g_amb[p] = (unsigned)row * 8192u + (unsigned)(c0 + c);
        }
        if (cond) bits |= (1ull << c);
    }
    g_mask[(size_t)row * MASK_W + cb] = bits;
}

// ---------------- K5: fixup + serial greedy NMS (1 warp, register mask) + output ----
__device__ __forceinline__ void prefetch_rows(int i, int l) {
    if (l < 30) {
        #pragma unroll
        for (int k = 0; k < 2; k++) {
            int p = l + 30 * k;                 // 0..59
            int d = 1 + p / 6;                  // 1..10
            int line = p % 6;                   // 0..5
            int r2 = i + d;
            if (r2 < PRE_N) {
                const char* ptr = (const char*)(g_mask + (size_t)r2 * MASK_W) + line * 128;
                asm volatile("prefetch.global.L1 [%0];" :: "l"(ptr));
            }
        }
    }
}

__global__ void __launch_bounds__(32, 1) k_nms_out(float* __restrict__ out) {
    __shared__ int kept[POST_N];
    int l = threadIdx.x;

    unsigned namb = g_amb_count;
    if (namb > AMB_CAP) namb = AMB_CAP;
    for (unsigned e = l; e < namb; e += 32) {
        unsigned pk = g_amb[e];
        int row = (int)(pk / 8192u), colk = (int)(pk % 8192u);
        float4 rbx = g_top_boxes[row];
        float4 cbx = g_top_boxes[colk];
        float rarea = (rbx.z - rbx.x) * (rbx.w - rbx.y);
        float carea = (cbx.z - cbx.x) * (cbx.w - cbx.y);
        float xx1 = fmaxf(rbx.x, cbx.x), yy1 = fmaxf(rbx.y, cbx.y);
        float xx2 = fminf(rbx.z, cbx.z), yy2 = fminf(rbx.w, cbx.w);
        float w = fmaxf(xx2 - xx1, 0.f), h = fmaxf(yy2 - yy1, 0.f);
        float inter = w * h;
        float den   = (rarea + carea) - inter;
        float iou   = __fdiv_rn(inter, den);
        unsigned long long bit = 1ull << (colk & 63);
        unsigned long long* word = &g_mask[(size_t)row * MASK_W + (colk >> 6)];
        if (iou > NMS_TH) atomicOr(word, bit);
        else              atomicAnd(word, ~bit);
    }
    __threadfence_block();
    __syncwarp();

    prefetch_rows(-1, l);

    unsigned long long s0 = g_invalid[l];
    unsigned long long s1 = g_invalid[l + 32];
    unsigned long long s2 = (l < 30) ? g_invalid[l + 64] : ~0ull;
    if (l == 29) s2 |= ~((1ull << 48) - 1ull);

    int cnt = 0;
    while (cnt < POST_N) {
        unsigned long long c0 = ~s0, c1 = ~s1, c2 = ~s2;
        unsigned cand;
        if (c0)      cand = (unsigned)((l << 6)        + __ffsll((long long)c0) - 1);
        else if (c1) cand = (unsigned)(((l + 32) << 6) + __ffsll((long long)c1) - 1);
        else if (c2) cand = (unsigned)(((l + 64) << 6) + __ffsll((long long)c2) - 1);
        else         cand = 0x7FFFFFFFu;
        unsigned i = __reduce_min_sync(0xFFFFFFFFu, cand);
        if (i >= PRE_N) break;

        if (l == 0) kept[cnt] = (int)i;
        cnt++;

        prefetch_rows((int)i, l);

        const unsigned long long* row = g_mask + (size_t)i * MASK_W;
        s0 |= __ldg(&row[l]);
        s1 |= __ldg(&row[l + 32]);
        if (l < 30) s2 |= __ldg(&row[l + 64]);
    }
    __syncwarp();

    for (int r = l; r < POST_N; r += 32) {
        float4 b4 = (r < cnt) ? g_top_boxes[kept[r]] : make_float4(0.f, 0.f, 0.f, 0.f);
        out[r * 5 + 0] = 0.f;
        out[r * 5 + 1] = b4.x;
        out[r * 5 + 2] = b4.y;
        out[r * 5 + 3] = b4.z;
        out[r * 5 + 4] = b4.w;
    }
}

// ---------------- launch ----------------
extern "C" void kernel_launch(void* const* d_in, const int* in_sizes, int n_in,
                              void* d_out, int out_size) {
    const float* scores  = (const float*)d_in[0];
    const float* deltas  = (const float*)d_in[1];
    const float* im_info = (const float*)d_in[2];
    float* out = (float*)d_out;
    (void)in_sizes; (void)n_in; (void)out_size;

    k_decode      <<<(NTOT / 4 + 255) / 256, 256>>>(scores, deltas, im_info);
    k_thresh      <<<1, 1024>>>();
    k_compact_rank<<<CR_BLOCKS, 256>>>();
    k_mask        <<<dim3(MASK_W, MASK_W), 64>>>();
    k_nms_out     <<<1, 32>>>(out);
}